// round 1
// baseline (speedup 1.0000x reference)
#include <cuda_runtime.h>

// MPA_37056977830474 — M=4, F=4, V=6 fixed-shape message-passing step.
// Single block, 128 threads; everything staged in shared memory.
//
// Input order: [0]num_M [1]num_FN [2]num_VN [3]IVF(4x4x6 f32)
//              [4]VN_index(2x6 i32) [5]m(i32) [6]n(i32)
//              [7]FN_index(4x3 i32) [8]fa_n(4x4x4x4 f32) [9]w0(4x4x6 f32)
// Output: 4x4x6 f32.

#define M_ 4
#define F_ 4
#define V_ 6

__global__ void mpa_kernel(const float* __restrict__ IVF,
                           const int*   __restrict__ VN_index,
                           const int*   __restrict__ m_ptr,
                           const int*   __restrict__ n_ptr,
                           const int*   __restrict__ FN_index,
                           const float* __restrict__ fa_n,
                           const float* __restrict__ w0,
                           float*       __restrict__ out) {
    __shared__ float s_IVF[M_][F_][V_];     // 96
    __shared__ float s_fa[F_][M_][M_][M_];  // 256
    __shared__ float s_g[3][M_][F_];        // g[k][b][f]
    __shared__ float s_IFV[M_][F_][V_];     // 96
    __shared__ float s_mean[F_][V_];        // 24
    __shared__ int   s_FN[F_ * 3];          // 12
    __shared__ int   s_VN[2 * V_];          // 12

    const int tid = threadIdx.x;

    // ---- stage inputs ----
    if (tid < M_ * F_ * V_) ((float*)s_IVF)[tid] = IVF[tid];
    for (int i = tid; i < F_ * M_ * M_ * M_; i += blockDim.x)
        ((float*)s_fa)[i] = fa_n[i];
    if (tid < F_ * 3)  s_FN[tid] = FN_index[tid];
    if (tid < 2 * V_)  s_VN[tid] = VN_index[tid];
    if (tid < M_ * F_ * V_) ((float*)s_IFV)[tid] = 0.0f;
    __syncthreads();

    // ---- gather g0/g1/g2: g[k][b][f] = IVF[b, f, FN[f][k]] ----
    if (tid < 3 * M_ * F_) {
        int k = tid >> 4;           // 0..2
        int r = tid & 15;
        int b = r >> 2;             // 0..3
        int f = r & 3;              // 0..3
        s_g[k][b][f] = s_IVF[b][f][s_FN[f * 3 + k]];
    }
    __syncthreads();

    // ---- contractions + scatter into IFV ----
    // A0[a,f] = sum_{b,c} g1[b,f] g2[c,f] fa[f][c][a][b]   -> IFV[a, f, FN[f][0]]
    // A1[a,f] = sum_{b,c} g0[b,f] g2[c,f] fa[f][c][b][a]   -> IFV[a, f, FN[f][1]]
    // A2[a,f] = sum_{b,c} g0[b,f] g1[c,f] fa[f][a][b][c]   -> IFV[a, f, FN[f][2]]
    if (tid < 3 * M_ * F_) {
        int k = tid >> 4;
        int r = tid & 15;
        int a = r >> 2;
        int f = r & 3;
        float acc = 0.0f;
        #pragma unroll
        for (int b = 0; b < M_; b++) {
            #pragma unroll
            for (int c = 0; c < M_; c++) {
                float p;
                if (k == 0)      p = s_g[1][b][f] * s_g[2][c][f] * s_fa[f][c][a][b];
                else if (k == 1) p = s_g[0][b][f] * s_g[2][c][f] * s_fa[f][c][b][a];
                else             p = s_g[0][b][f] * s_g[1][c][f] * s_fa[f][a][b][c];
                acc += p;
            }
        }
        // FN row entries are distinct -> no write collisions
        s_IFV[a][f][s_FN[f * 3 + k]] = acc;
    }
    __syncthreads();

    // ---- mean over a ----
    if (tid < F_ * V_) {
        int f = tid / V_;
        int v = tid % V_;
        s_mean[f][v] = 0.25f * (s_IFV[0][f][v] + s_IFV[1][f][v] +
                                s_IFV[2][f][v] + s_IFV[3][f][v]);
    }
    __syncthreads();

    // ---- output ----
    const int mm = m_ptr[0];
    const int nn = n_ptr[0];
    if (tid < M_ * F_ * V_) {
        int a = tid / (F_ * V_);
        int r = tid % (F_ * V_);
        int f = r / V_;
        int v = r % V_;
        float val = s_IVF[a][f][v];
        if (mm < nn) {
            int va = s_VN[v];        // row 0
            int vb = s_VN[V_ + v];   // row 1
            if (f == va)      val = 0.25f * s_IFV[a][vb][v] / s_mean[vb][v];
            else if (f == vb) val = 0.25f * s_IFV[a][va][v] / s_mean[va][v];
            val *= w0[tid];
        }
        out[tid] = val;
    }
}

extern "C" void kernel_launch(void* const* d_in, const int* in_sizes, int n_in,
                              void* d_out, int out_size) {
    const float* IVF      = (const float*)d_in[3];
    const int*   VN_index = (const int*)  d_in[4];
    const int*   m_ptr    = (const int*)  d_in[5];
    const int*   n_ptr    = (const int*)  d_in[6];
    const int*   FN_index = (const int*)  d_in[7];
    const float* fa_n     = (const float*)d_in[8];
    const float* w0       = (const float*)d_in[9];
    float* out = (float*)d_out;

    mpa_kernel<<<1, 128>>>(IVF, VN_index, m_ptr, n_ptr, FN_index, fa_n, w0, out);
}

// round 2
// speedup vs baseline: 1.3454x; 1.3454x over previous
#include <cuda_runtime.h>

// MPA_37056977830474 — M=4, F=4, V=6 fixed-shape message-passing step.
// Single WARP (32 threads): no BAR.SYNC, only 2 x WARPSYNC on the critical path.
//
// Input order: [0]num_M [1]num_FN [2]num_VN [3]IVF(4x4x6 f32)
//              [4]VN_index(2x6 i32) [5]m(i32) [6]n(i32)
//              [7]FN_index(4x3 i32) [8]fa_n(4x4x4x4 f32) [9]w0(4x4x6 f32)
// Output: 4x4x6 f32.

#define M_ 4
#define F_ 4
#define V_ 6

__global__ void __launch_bounds__(32, 1)
mpa_kernel(const float* __restrict__ IVF,
           const int*   __restrict__ VN_index,
           const int*   __restrict__ m_ptr,
           const int*   __restrict__ n_ptr,
           const int*   __restrict__ FN_index,
           const float* __restrict__ fa_n,
           const float* __restrict__ w0,
           float*       __restrict__ out) {
    __shared__ float s_IVF[M_ * F_ * V_];          // 96, flat [a*24 + f*6 + v]
    __shared__ float s_fa[F_][M_][M_][M_];         // 256, [f][c?][..] per layout below
    __shared__ float s_IFV[M_][F_][V_];            // 96
    __shared__ int   s_FN[F_ * 3];                 // 12
    __shared__ int   s_VN[2 * V_];                 // 12

    const int t = threadIdx.x;  // 0..31

    // ---- stage (all loads issued up-front, high MLP) ----
    // fa_n: 256 floats = 64 float4; threads load t and t+32
    {
        const float4* fsrc = (const float4*)fa_n;
        float4* fdst = (float4*)s_fa;
        fdst[t]      = fsrc[t];
        fdst[t + 32] = fsrc[t + 32];
    }
    // IVF: 96 floats = 24 float4
    if (t < 24) ((float4*)s_IVF)[t] = ((const float4*)IVF)[t];
    if (t < 12) { s_FN[t] = FN_index[t]; s_VN[t] = VN_index[t]; }
    // zero IFV (scatter only fills 48 of 96; rest must be 0 for the mean)
    {
        float* z = (float*)s_IFV;
        z[t] = 0.0f; z[t + 32] = 0.0f; z[t + 64] = 0.0f;
    }
    // preload the tail-phase operands into registers so their latency overlaps
    const int   mm = m_ptr[0];
    const int   nn = n_ptr[0];
    float rw0 = w0[t], rw1 = w0[t + 32], rw2 = w0[t + 64];

    __syncwarp();

    // ---- contractions + scatter into IFV (48 tasks, 2 per thread max) ----
    // task id = k*16 + a*4 + f
    //   k=0: A0[a,f] = sum_{b,c} g1[b,f] g2[c,f] fa[f][c][a][b] -> IFV[a,f,FN[f,0]]
    //   k=1: A1[a,f] = sum_{b,c} g0[b,f] g2[c,f] fa[f][c][b][a] -> IFV[a,f,FN[f,1]]
    //   k=2: A2[a,f] = sum_{b,c} g0[b,f] g1[c,f] fa[f][a][b][c] -> IFV[a,f,FN[f,2]]
    // gk[b,f] = IVF[b, f, FN[f,k]]
    #pragma unroll
    for (int rep = 0; rep < 2; rep++) {
        int id = t + rep * 32;
        if (id < 48) {
            int k = id >> 4;
            int r = id & 15;
            int a = r >> 2;
            int f = r & 3;
            // the two g-vectors this task needs
            int k1 = (k == 0) ? 1 : 0;           // first factor's FN column
            int k2 = (k == 2) ? 1 : 2;           // second factor's FN column
            int col1 = s_FN[f * 3 + k1];
            int col2 = s_FN[f * 3 + k2];
            float gx[M_], gy[M_];
            #pragma unroll
            for (int b = 0; b < M_; b++) {
                gx[b] = s_IVF[b * (F_ * V_) + f * V_ + col1];
                gy[b] = s_IVF[b * (F_ * V_) + f * V_ + col2];
            }
            float acc = 0.0f;
            #pragma unroll
            for (int b = 0; b < M_; b++) {
                #pragma unroll
                for (int c = 0; c < M_; c++) {
                    float fv;
                    if (k == 0)      fv = s_fa[f][c][a][b];
                    else if (k == 1) fv = s_fa[f][c][b][a];
                    else             fv = s_fa[f][a][b][c];
                    acc += gx[b] * gy[c] * fv;
                }
            }
            s_IFV[a][f][s_FN[f * 3 + k]] = acc;  // distinct cols per row: no collision
        }
    }

    __syncwarp();

    // ---- output: 3 elements per thread; mean fused in (IFV/sum == (IFV/M)/(sum/M)) ----
    const bool doUpdate = (mm < nn);
    #pragma unroll
    for (int j = 0; j < 3; j++) {
        int idx = t + j * 32;
        int a = idx / (F_ * V_);
        int r = idx % (F_ * V_);
        int f = r / V_;
        int v = r % V_;
        float val = s_IVF[idx];
        if (doUpdate) {
            int va = s_VN[v];
            int vb = s_VN[V_ + v];
            int src = -1;
            if (f == va)      src = vb;
            else if (f == vb) src = va;
            if (src >= 0) {
                float sum = s_IFV[0][src][v] + s_IFV[1][src][v] +
                            s_IFV[2][src][v] + s_IFV[3][src][v];
                val = __fdividef(s_IFV[a][src][v], sum);
            }
            val *= (j == 0 ? rw0 : (j == 1 ? rw1 : rw2));
        }
        out[idx] = val;
    }
}

extern "C" void kernel_launch(void* const* d_in, const int* in_sizes, int n_in,
                              void* d_out, int out_size) {
    const float* IVF      = (const float*)d_in[3];
    const int*   VN_index = (const int*)  d_in[4];
    const int*   m_ptr    = (const int*)  d_in[5];
    const int*   n_ptr    = (const int*)  d_in[6];
    const int*   FN_index = (const int*)  d_in[7];
    const float* fa_n     = (const float*)d_in[8];
    const float* w0       = (const float*)d_in[9];
    float* out = (float*)d_out;

    mpa_kernel<<<1, 32>>>(IVF, VN_index, m_ptr, n_ptr, FN_index, fa_n, w0, out);
}

// round 3
// speedup vs baseline: 1.3523x; 1.0052x over previous
#include <cuda_runtime.h>

// MPA_37056977830474 — M=4, F=4, V=6 fixed-shape message-passing step.
// Single warp. Minimal critical path:
//  - fa_n, FN_index, VN_index, w0, m, n loaded DIRECTLY into registers at
//    static per-thread addresses, all issued at kernel entry (full MLP overlap).
//  - Only IVF (dynamic-column gather) and IFV (cross-lane exchange) use SMEM.
//  - Exactly 2 __syncwarp on the critical path.
//
// Input order: [0]num_M [1]num_FN [2]num_VN [3]IVF(4x4x6 f32)
//              [4]VN_index(2x6 i32) [5]m(i32) [6]n(i32)
//              [7]FN_index(4x3 i32) [8]fa_n(4x4x4x4 f32) [9]w0(4x4x6 f32)
// Output: 4x4x6 f32.

#define M_ 4
#define F_ 4
#define V_ 6
#define FV (F_ * V_)   // 24

__global__ void __launch_bounds__(32, 1)
mpa_kernel(const float* __restrict__ IVF,
           const int*   __restrict__ VN_index,
           const int*   __restrict__ m_ptr,
           const int*   __restrict__ n_ptr,
           const int*   __restrict__ FN_index,
           const float* __restrict__ fa_n,
           const float* __restrict__ w0,
           float*       __restrict__ out) {
    __shared__ float s_IVF[M_ * FV];        // 96, [a*24 + f*6 + v]
    __shared__ float s_IFV[M_ * FV];        // 96, same layout

    const int t = threadIdx.x;  // 0..31

    // ================= stage phase: issue every global load up front =========
    // IVF -> SMEM (24 x float4)
    if (t < 24) ((float4*)s_IVF)[t] = ((const float4*)IVF)[t];
    // zero IFV (scatter fills only 48 of 96)
    s_IFV[t] = 0.0f; s_IFV[t + 32] = 0.0f; s_IFV[t + 64] = 0.0f;

    // tail-phase operands (static per-thread addresses)
    const int mm = m_ptr[0];
    const int nn = n_ptr[0];
    float rw[3];
    int   vva[3], vvb[3];
    #pragma unroll
    for (int j = 0; j < 3; j++) {
        int idx = t + j * 32;           // 0..95
        int v = idx % V_;
        rw[j]  = w0[idx];
        vva[j] = VN_index[v];
        vvb[j] = VN_index[V_ + v];
    }

    // contraction tasks: id = k*16 + a*4 + f, 48 tasks, <=2 per lane.
    //   k=0: A0[a,f] = sum_{b,c} g1[b,f] g2[c,f] fa[f][c][a][b] -> IFV[a,f,FN[f,0]]
    //   k=1: A1[a,f] = sum_{b,c} g0[b,f] g2[c,f] fa[f][c][b][a] -> IFV[a,f,FN[f,1]]
    //   k=2: A2[a,f] = sum_{b,c} g0[b,f] g1[c,f] fa[f][a][b][c] -> IFV[a,f,FN[f,2]]
    // All fa addresses are static per task: load into registers now.
    int   c1[2], c2[2], ck[2];
    float fv[2][16];
    int   ka[2], aa[2], ff[2];
    bool  act[2];
    #pragma unroll
    for (int rep = 0; rep < 2; rep++) {
        int id = t + rep * 32;
        act[rep] = (id < 48);
        int k = (id >> 4) & 3, r = id & 15, a = r >> 2, f = r & 3;
        ka[rep] = k; aa[rep] = a; ff[rep] = f;
        if (act[rep]) {
            int k1 = (k == 0) ? 1 : 0;
            int k2 = (k == 2) ? 1 : 2;
            c1[rep] = FN_index[f * 3 + k1];
            c2[rep] = FN_index[f * 3 + k2];
            ck[rep] = FN_index[f * 3 + k];
            // fa[f][c][a][b] / fa[f][c][b][a] / fa[f][a][b][c] as base + b*cb + c*cc
            int cb   = (k == 0) ? 1 : 4;
            int cc   = (k == 2) ? 1 : 16;
            int base = f * 64 + ((k == 0) ? a * 4 : (k == 1) ? a : a * 16);
            #pragma unroll
            for (int b = 0; b < M_; b++)
                #pragma unroll
                for (int c = 0; c < M_; c++)
                    fv[rep][b * 4 + c] = __ldg(&fa_n[base + b * cb + c * cc]);
        }
    }

    __syncwarp();

    // ================= contraction + scatter =================================
    #pragma unroll
    for (int rep = 0; rep < 2; rep++) {
        if (act[rep]) {
            int f = ff[rep];
            float gx[M_], gy[M_];
            #pragma unroll
            for (int b = 0; b < M_; b++) {
                gx[b] = s_IVF[b * FV + f * V_ + c1[rep]];
                gy[b] = s_IVF[b * FV + f * V_ + c2[rep]];
            }
            float acc = 0.0f;
            #pragma unroll
            for (int b = 0; b < M_; b++)
                #pragma unroll
                for (int c = 0; c < M_; c++)
                    acc += gx[b] * gy[c] * fv[rep][b * 4 + c];
            // distinct columns per (a,f) row -> no collisions
            s_IFV[aa[rep] * FV + f * V_ + ck[rep]] = acc;
        }
    }

    __syncwarp();

    // ================= output (mean fused: IFV/sum == (IFV/M)/(sum/M)) =======
    const bool doUpdate = (mm < nn);
    #pragma unroll
    for (int j = 0; j < 3; j++) {
        int idx = t + j * 32;
        int a = idx / FV;
        int r = idx % FV;
        int f = r / V_;
        int v = r % V_;
        float val = s_IVF[idx];
        if (doUpdate) {
            int va = vva[j], vb = vvb[j];
            int src = (f == va) ? vb : (f == vb) ? va : -1;
            if (src >= 0) {
                int base = src * V_ + v;
                float sum = s_IFV[base] + s_IFV[base + FV] +
                            s_IFV[base + 2 * FV] + s_IFV[base + 3 * FV];
                val = __fdividef(s_IFV[a * FV + base], sum);
            }
            val *= rw[j];
        }
        out[idx] = val;
    }
}

extern "C" void kernel_launch(void* const* d_in, const int* in_sizes, int n_in,
                              void* d_out, int out_size) {
    const float* IVF      = (const float*)d_in[3];
    const int*   VN_index = (const int*)  d_in[4];
    const int*   m_ptr    = (const int*)  d_in[5];
    const int*   n_ptr    = (const int*)  d_in[6];
    const int*   FN_index = (const int*)  d_in[7];
    const float* fa_n     = (const float*)d_in[8];
    const float* w0       = (const float*)d_in[9];
    float* out = (float*)d_out;

    mpa_kernel<<<1, 32>>>(IVF, VN_index, m_ptr, n_ptr, FN_index, fa_n, w0, out);
}

// round 4
// speedup vs baseline: 1.5818x; 1.1697x over previous
#include <cuda_runtime.h>

// MPA_37056977830474 — M=4, F=4, V=6 fixed-shape message-passing step.
// Single warp, per-k lane specialization:
//   lanes 0..15  : tasks (k=0) and (k=2) for (a,f)=(t>>2, t&3)  [fa via float4]
//   lanes 16..31 : task  (k=1) for (a,f)                         [fa scalar]
// All static-address operands (fa_n, FN, VN, w0, m, n) go straight to
// registers at entry; only IVF (dynamic gather) and IFV (exchange) use SMEM.
// Two __syncwarp total; tree-structured dot products.
//
// Input order: [0]num_M [1]num_FN [2]num_VN [3]IVF(4x4x6 f32)
//              [4]VN_index(2x6 i32) [5]m(i32) [6]n(i32)
//              [7]FN_index(4x3 i32) [8]fa_n(4x4x4x4 f32) [9]w0(4x4x6 f32)
// Output: 4x4x6 f32.

#define M_ 4
#define F_ 4
#define V_ 6
#define FV (F_ * V_)   // 24

__global__ void __launch_bounds__(32, 1)
mpa_kernel(const float* __restrict__ IVF,
           const int*   __restrict__ VN_index,
           const int*   __restrict__ m_ptr,
           const int*   __restrict__ n_ptr,
           const int*   __restrict__ FN_index,
           const float* __restrict__ fa_n,
           const float* __restrict__ w0,
           float*       __restrict__ out) {
    __shared__ float s_IVF[M_ * FV];   // [a*24 + f*6 + v]
    __shared__ float s_IFV[M_ * FV];

    const int t = threadIdx.x;          // 0..31
    const bool lo = (t < 16);
    const int u = lo ? t : (t - 16);
    const int a = (u >> 2) & 3;
    const int f = u & 3;

    // ================= stage: every global load issued up front ==============
    if (t < 24) ((float4*)s_IVF)[t] = ((const float4*)IVF)[t];
    s_IFV[t] = 0.0f; s_IFV[t + 32] = 0.0f; s_IFV[t + 64] = 0.0f;

    const int mm = m_ptr[0];
    const int nn = n_ptr[0];

    // output-phase operands (static per-thread)
    float rw[3]; int vva[3], vvb[3];
    #pragma unroll
    for (int j = 0; j < 3; j++) {
        int idx = t + j * 32;
        int v = idx % V_;
        rw[j]  = w0[idx];
        vva[j] = VN_index[v];
        vvb[j] = VN_index[V_ + v];
    }

    // FN columns for this lane's f (static addresses)
    const int col0 = FN_index[f * 3 + 0];
    const int col1 = FN_index[f * 3 + 1];
    const int col2 = FN_index[f * 3 + 2];

    // fa coefficients (static addresses; issue now, consume after sync)
    const float4* fa4 = (const float4*)fa_n;
    float4 q[4], r[4];      // lanes<16: q[c]=fa[f][c][a][.b]  r[b]=fa[f][a][b][.c]
    float  fvs[16];         // lanes>=16: fvs[b*4+c]=fa[f][c][b][a]
    if (lo) {
        #pragma unroll
        for (int c = 0; c < 4; c++) q[c] = fa4[f * 16 + c * 4 + a];
        #pragma unroll
        for (int b = 0; b < 4; b++) r[b] = fa4[f * 16 + a * 4 + b];
    } else {
        #pragma unroll
        for (int b = 0; b < 4; b++)
            #pragma unroll
            for (int c = 0; c < 4; c++)
                fvs[b * 4 + c] = __ldg(&fa_n[f * 64 + c * 16 + b * 4 + a]);
    }

    __syncwarp();

    // ================= contraction + scatter =================================
    //  k=0: A0[a,f]=Σ_{b,c} g1[b]g2[c] fa[f][c][a][b] -> IFV[a,f,col0]
    //  k=1: A1[a,f]=Σ_{b,c} g0[b]g2[c] fa[f][c][b][a] -> IFV[a,f,col1]
    //  k=2: A2[a,f]=Σ_{b,c} g0[b]g1[c] fa[f][a][b][c] -> IFV[a,f,col2]
    const int gbase = f * V_;
    if (lo) {
        float g0[4], g1[4], g2[4];
        #pragma unroll
        for (int b = 0; b < 4; b++) {
            g0[b] = s_IVF[b * FV + gbase + col0];
            g1[b] = s_IVF[b * FV + gbase + col1];
            g2[b] = s_IVF[b * FV + gbase + col2];
        }
        // acc0 = Σ_c g2[c] * (g1 · q[c])
        float d0 = fmaf(g1[3], q[0].w, fmaf(g1[2], q[0].z, fmaf(g1[1], q[0].y, g1[0] * q[0].x)));
        float d1 = fmaf(g1[3], q[1].w, fmaf(g1[2], q[1].z, fmaf(g1[1], q[1].y, g1[0] * q[1].x)));
        float d2 = fmaf(g1[3], q[2].w, fmaf(g1[2], q[2].z, fmaf(g1[1], q[2].y, g1[0] * q[2].x)));
        float d3 = fmaf(g1[3], q[3].w, fmaf(g1[2], q[3].z, fmaf(g1[1], q[3].y, g1[0] * q[3].x)));
        float acc0 = fmaf(g2[3], d3, fmaf(g2[2], d2, fmaf(g2[1], d1, g2[0] * d0)));
        // acc2 = Σ_b g0[b] * (g1 · r[b])
        float e0 = fmaf(g1[3], r[0].w, fmaf(g1[2], r[0].z, fmaf(g1[1], r[0].y, g1[0] * r[0].x)));
        float e1 = fmaf(g1[3], r[1].w, fmaf(g1[2], r[1].z, fmaf(g1[1], r[1].y, g1[0] * r[1].x)));
        float e2 = fmaf(g1[3], r[2].w, fmaf(g1[2], r[2].z, fmaf(g1[1], r[2].y, g1[0] * r[2].x)));
        float e3 = fmaf(g1[3], r[3].w, fmaf(g1[2], r[3].z, fmaf(g1[1], r[3].y, g1[0] * r[3].x)));
        float acc2 = fmaf(g0[3], e3, fmaf(g0[2], e2, fmaf(g0[1], e1, g0[0] * e0)));
        s_IFV[a * FV + gbase + col0] = acc0;   // distinct cols: no collisions
        s_IFV[a * FV + gbase + col2] = acc2;
    } else {
        float g0[4], g2[4];
        #pragma unroll
        for (int b = 0; b < 4; b++) {
            g0[b] = s_IVF[b * FV + gbase + col0];
            g2[b] = s_IVF[b * FV + gbase + col2];
        }
        // acc1 = Σ_b g0[b] * (Σ_c g2[c] fvs[b*4+c])
        float acc1 = 0.0f;
        #pragma unroll
        for (int b = 0; b < 4; b++) {
            float d = fmaf(g2[3], fvs[b * 4 + 3],
                      fmaf(g2[2], fvs[b * 4 + 2],
                      fmaf(g2[1], fvs[b * 4 + 1], g2[0] * fvs[b * 4 + 0])));
            acc1 = fmaf(g0[b], d, acc1);
        }
        s_IFV[a * FV + gbase + col1] = acc1;
    }

    __syncwarp();

    // ================= output (mean fused: IFV/sum == (IFV/M)/(sum/M)) =======
    const bool doUpdate = (mm < nn);
    #pragma unroll
    for (int j = 0; j < 3; j++) {
        int idx = t + j * 32;
        int oa = idx / FV;
        int rr = idx % FV;
        int of = rr / V_;
        int ov = rr % V_;
        float val = s_IVF[idx];
        if (doUpdate) {
            int va = vva[j], vb = vvb[j];
            int src = (of == va) ? vb : (of == vb) ? va : -1;
            if (src >= 0) {
                int base = src * V_ + ov;
                float sum = s_IFV[base] + s_IFV[base + FV] +
                            s_IFV[base + 2 * FV] + s_IFV[base + 3 * FV];
                val = __fdividef(s_IFV[oa * FV + base], sum);
            }
            val *= rw[j];
        }
        out[idx] = val;
    }
}

extern "C" void kernel_launch(void* const* d_in, const int* in_sizes, int n_in,
                              void* d_out, int out_size) {
    const float* IVF      = (const float*)d_in[3];
    const int*   VN_index = (const int*)  d_in[4];
    const int*   m_ptr    = (const int*)  d_in[5];
    const int*   n_ptr    = (const int*)  d_in[6];
    const int*   FN_index = (const int*)  d_in[7];
    const float* fa_n     = (const float*)d_in[8];
    const float* w0       = (const float*)d_in[9];
    float* out = (float*)d_out;

    mpa_kernel<<<1, 32>>>(IVF, VN_index, m_ptr, n_ptr, FN_index, fa_n, w0, out);
}